// round 1
// baseline (speedup 1.0000x reference)
#include <cuda_runtime.h>
#include <math_constants.h>

// DotProductGraphAttention: B=8,H=8,N=1024,d=128
// out = softmax(mask(QK^T/8, adj)) @ V, written contiguously in (B,H,N,d) order
// (the reference's reshape to (N,B,H,d) is a raw view: identical flat layout).

namespace {
constexpr int Nq  = 1024;
constexpr int D   = 128;
constexpr int BHn = 64;     // B*H heads
constexpr int BR  = 32;     // query rows per block
constexpr int BC  = 64;     // key cols per tile
constexpr int TPB = 256;

constexpr int QS = D + 4;   // padded row strides (floats) for bank-conflict avoidance
constexpr int KS = D + 4;
constexpr int VS = D + 4;
constexpr int PS = BC + 4;

constexpr int SMEM_FLOATS = BR * QS + BC * KS + BC * VS + BR * PS;
constexpr int SMEM_BYTES  = SMEM_FLOATS * 4;   // 93184 bytes -> 2 CTAs/SM
}

__global__ __launch_bounds__(TPB, 2)
void fa32_kernel(const float* __restrict__ Qg, const float* __restrict__ Kg,
                 const float* __restrict__ Vg, const int* __restrict__ adj,
                 float* __restrict__ Out)
{
    extern __shared__ float sm[];
    float* Qs  = sm;                    // [BR][QS]
    float* Ksm = Qs  + BR * QS;         // [BC][KS]
    float* Vsm = Ksm + BC * KS;         // [BC][VS]
    float* Psm = Vsm + BC * VS;         // [BR][PS]

    const int tid  = threadIdx.x;
    const int tx   = tid & 15;          // 16 col-threads
    const int ty   = tid >> 4;          // 16 row-threads
    const int head = blockIdx.x >> 5;   // 0..63
    const int rt   = blockIdx.x & 31;   // row tile 0..31
    const int row0 = rt * BR;

    const float* Qh = Qg + (size_t)head * Nq * D;
    const float* Kh = Kg + (size_t)head * Nq * D;
    const float* Vh = Vg + (size_t)head * Nq * D;

    // ---- load Q tile (32x128) ----
    #pragma unroll
    for (int i = 0; i < (BR * D) / (4 * TPB); ++i) {   // 4 float4 per thread
        int f  = tid + i * TPB;
        int r  = f >> 5;                 // 32 float4 per row
        int kq = f & 31;
        float4 v = *(const float4*)(Qh + (size_t)(row0 + r) * D + kq * 4);
        *(float4*)(Qs + r * QS + kq * 4) = v;
    }

    const int r0 = 2 * ty;              // this thread's two query rows
    const int c0 = 4 * tx;              // score cols c0..c0+3

    float acc[2][2][4];                 // [row][u][i]: out cols u*64 + 4*tx + i
    #pragma unroll
    for (int r = 0; r < 2; ++r)
        #pragma unroll
        for (int u = 0; u < 2; ++u)
            #pragma unroll
            for (int i = 0; i < 4; ++i) acc[r][u][i] = 0.f;

    float mrow[2] = {-CUDART_INF_F, -CUDART_INF_F};
    float lrow[2] = {0.f, 0.f};

    for (int kt = 0; kt < Nq / BC; ++kt) {
        __syncthreads();   // prior AV reads of Vsm/Psm done before overwrite
        // ---- load K,V tiles (64x128 each) ----
        #pragma unroll
        for (int i = 0; i < (BC * D) / (4 * TPB); ++i) {  // 8 float4 per thread
            int f  = tid + i * TPB;
            int r  = f >> 5;
            int kq = f & 31;
            const size_t g = (size_t)(kt * BC + r) * D + kq * 4;
            *(float4*)(Ksm + r * KS + kq * 4) = *(const float4*)(Kh + g);
            *(float4*)(Vsm + r * VS + kq * 4) = *(const float4*)(Vh + g);
        }
        __syncthreads();

        // ---- S = Q K^T  (2 rows x 4 cols per thread) ----
        float s[2][4] = {{0.f,0.f,0.f,0.f},{0.f,0.f,0.f,0.f}};
        #pragma unroll 8
        for (int k = 0; k < D; k += 4) {
            float4 q0 = *(const float4*)(Qs + r0 * QS + k);
            float4 q1 = *(const float4*)(Qs + (r0 + 1) * QS + k);
            #pragma unroll
            for (int c = 0; c < 4; ++c) {
                float4 kv = *(const float4*)(Ksm + (c0 + c) * KS + k);
                s[0][c] += q0.x * kv.x; s[0][c] += q0.y * kv.y;
                s[0][c] += q0.z * kv.z; s[0][c] += q0.w * kv.w;
                s[1][c] += q1.x * kv.x; s[1][c] += q1.y * kv.y;
                s[1][c] += q1.z * kv.z; s[1][c] += q1.w * kv.w;
            }
        }

        // ---- mask + scale (exact reference constants) ----
        const int gr0 = row0 + r0;
        const int gc  = kt * BC + c0;
        int4 a0 = *(const int4*)(adj + (size_t)gr0 * Nq + gc);
        int4 a1 = *(const int4*)(adj + (size_t)(gr0 + 1) * Nq + gc);
        s[0][0] = (a0.x > 0) ? s[0][0] * 0.125f : -9e15f;
        s[0][1] = (a0.y > 0) ? s[0][1] * 0.125f : -9e15f;
        s[0][2] = (a0.z > 0) ? s[0][2] * 0.125f : -9e15f;
        s[0][3] = (a0.w > 0) ? s[0][3] * 0.125f : -9e15f;
        s[1][0] = (a1.x > 0) ? s[1][0] * 0.125f : -9e15f;
        s[1][1] = (a1.y > 0) ? s[1][1] * 0.125f : -9e15f;
        s[1][2] = (a1.z > 0) ? s[1][2] * 0.125f : -9e15f;
        s[1][3] = (a1.w > 0) ? s[1][3] * 0.125f : -9e15f;

        // ---- online softmax update per row ----
        #pragma unroll
        for (int r = 0; r < 2; ++r) {
            float tm = fmaxf(fmaxf(s[r][0], s[r][1]), fmaxf(s[r][2], s[r][3]));
            #pragma unroll
            for (int off = 1; off < 16; off <<= 1)
                tm = fmaxf(tm, __shfl_xor_sync(0xffffffffu, tm, off));
            float mnew = fmaxf(mrow[r], tm);
            float sc   = __expf(mrow[r] - mnew);   // exp(-inf)=0 on first tile

            float p0 = __expf(s[r][0] - mnew);
            float p1 = __expf(s[r][1] - mnew);
            float p2 = __expf(s[r][2] - mnew);
            float p3 = __expf(s[r][3] - mnew);
            float rs = (p0 + p1) + (p2 + p3);
            #pragma unroll
            for (int off = 1; off < 16; off <<= 1)
                rs += __shfl_xor_sync(0xffffffffu, rs, off);

            lrow[r] = lrow[r] * sc + rs;
            mrow[r] = mnew;

            #pragma unroll
            for (int u = 0; u < 2; ++u)
                #pragma unroll
                for (int i = 0; i < 4; ++i) acc[r][u][i] *= sc;

            *(float4*)(Psm + (r0 + r) * PS + c0) = make_float4(p0, p1, p2, p3);
        }
        __syncthreads();

        // ---- O += P @ V  (2 rows x 8 cols per thread) ----
        #pragma unroll 4
        for (int m = 0; m < BC; m += 4) {
            float4 p0 = *(const float4*)(Psm + r0 * PS + m);
            float4 p1 = *(const float4*)(Psm + (r0 + 1) * PS + m);
            const float pw0[4] = {p0.x, p0.y, p0.z, p0.w};
            const float pw1[4] = {p1.x, p1.y, p1.z, p1.w};
            #pragma unroll
            for (int mm = 0; mm < 4; ++mm) {
                #pragma unroll
                for (int u = 0; u < 2; ++u) {
                    float4 vv = *(const float4*)(Vsm + (m + mm) * VS + u * 64 + 4 * tx);
                    acc[0][u][0] += pw0[mm] * vv.x; acc[0][u][1] += pw0[mm] * vv.y;
                    acc[0][u][2] += pw0[mm] * vv.z; acc[0][u][3] += pw0[mm] * vv.w;
                    acc[1][u][0] += pw1[mm] * vv.x; acc[1][u][1] += pw1[mm] * vv.y;
                    acc[1][u][2] += pw1[mm] * vv.z; acc[1][u][3] += pw1[mm] * vv.w;
                }
            }
        }
    }

    // ---- normalize + store (contiguous (B,H,N,d) == raw-reshaped (N,B,H,d)) ----
    #pragma unroll
    for (int r = 0; r < 2; ++r) {
        float inv = 1.0f / lrow[r];
        float* orow = Out + (size_t)(head * Nq + row0 + r0 + r) * D;
        #pragma unroll
        for (int u = 0; u < 2; ++u) {
            float4 o;
            o.x = acc[r][u][0] * inv;
            o.y = acc[r][u][1] * inv;
            o.z = acc[r][u][2] * inv;
            o.w = acc[r][u][3] * inv;
            *(float4*)(orow + u * 64 + 4 * tx) = o;
        }
    }
}

extern "C" void kernel_launch(void* const* d_in, const int* in_sizes, int n_in,
                              void* d_out, int out_size)
{
    const float* Q   = (const float*)d_in[0];
    const float* K   = (const float*)d_in[1];
    const float* V   = (const float*)d_in[2];
    const int*   adj = (const int*)d_in[3];
    float*       out = (float*)d_out;

    cudaFuncSetAttribute(fa32_kernel,
                         cudaFuncAttributeMaxDynamicSharedMemorySize, SMEM_BYTES);

    dim3 grid(BHn * (Nq / BR));   // 64 heads * 32 row-tiles = 2048 CTAs
    fa32_kernel<<<grid, TPB, SMEM_BYTES>>>(Q, K, V, adj, out);
}

// round 2
// speedup vs baseline: 7.2388x; 7.2388x over previous
#include <cuda_runtime.h>
#include <cstdint>

// Flash attention, tf32 mma.sync path.
// B=8,H=8,N=1024,d=128. out = softmax(mask(QK^T/8, adj)) @ V, (B,H,N,d) contiguous.

namespace {
constexpr int Nq  = 1024;
constexpr int D   = 128;
constexpr int BR  = 128;            // query rows per CTA
constexpr int BC  = 32;             // key cols per tile
constexpr int NT  = Nq / BC;        // 32 tiles
constexpr int TPB = 256;            // 8 warps, 16 query rows each

constexpr int QS = D + 4;           // 132: bank = 4g+c (unique for g0..7,c0..3)
constexpr int KSs = D + 4;          // 132: same pattern (rows span g)
constexpr int VS = D + 8;           // 136: bank = 8c+g (rows span c)
constexpr int PS = BC + 4;          // 36:  bank = 4g+c

constexpr int SM_Q = BR * QS;               // 16896
constexpr int SM_K = 2 * BC * KSs;          // 8448
constexpr int SM_V = 2 * BC * VS;           // 8704
constexpr int SM_P = 8 * 16 * PS;           // 4608
constexpr int SMEM_BYTES = (SM_Q + SM_K + SM_V + SM_P) * 4;  // 154,624 B
}

__device__ __forceinline__ float to_tf32(float x) {
    float r;
    asm("cvt.rna.tf32.f32 %0, %1;" : "=f"(r) : "f"(x));
    return r;
}

__device__ __forceinline__ uint32_t smem_u32(const void* p) {
    return (uint32_t)__cvta_generic_to_shared(p);
}

__device__ __forceinline__ void cp_async16(uint32_t s, const void* g) {
    asm volatile("cp.async.cg.shared.global [%0], [%1], 16;" :: "r"(s), "l"(g));
}

__device__ __forceinline__ void mma_tf32(float& d0, float& d1, float& d2, float& d3,
                                         uint32_t a0, uint32_t a1, uint32_t a2, uint32_t a3,
                                         uint32_t b0, uint32_t b1) {
    asm volatile("mma.sync.aligned.m16n8k8.row.col.f32.tf32.tf32.f32 "
                 "{%0,%1,%2,%3},{%4,%5,%6,%7},{%8,%9},{%0,%1,%2,%3};"
                 : "+f"(d0), "+f"(d1), "+f"(d2), "+f"(d3)
                 : "r"(a0), "r"(a1), "r"(a2), "r"(a3), "r"(b0), "r"(b1));
}

__device__ __forceinline__ uint32_t fu(float x) { return __float_as_uint(x); }

// FMA-only exp: avoids the 0.5/cyc/SM MUFU.EX2 floor (503us chip-wide for 67M exps).
// Valid for x <= ~0.1; clamps below -87. |rel err| ~1e-6.
__device__ __forceinline__ float exp_fast(float x) {
    x = fmaxf(x, -87.0f);
    float t = x * 1.4426950408889634f;
    float r = t + 12582912.0f;                       // 1.5*2^23 magic round
    int   n = __float_as_int(r) - 0x4B400000;        // integer part (two's complement ok)
    float f = t - (r - 12582912.0f);                 // f in [-0.5, 0.5]
    float p = 0.00133335581f;
    p = fmaf(p, f, 0.00961812910f);
    p = fmaf(p, f, 0.0555041087f);
    p = fmaf(p, f, 0.240226507f);
    p = fmaf(p, f, 0.693147180f);
    p = fmaf(p, f, 1.0f);                            // p = 2^f in [0.707, 1.415]
    return __int_as_float(__float_as_int(p) + (n << 23));
}

__global__ __launch_bounds__(TPB, 1)
void fa_tf32_kernel(const float* __restrict__ Qg, const float* __restrict__ Kg,
                    const float* __restrict__ Vg, const int* __restrict__ adj,
                    float* __restrict__ Out)
{
    extern __shared__ float sm[];
    float* Qs = sm;                       // [128][132]
    float* Kb = Qs + SM_Q;                // [2][32][132]
    float* Vb = Kb + SM_K;                // [2][32][136]
    float* Pa = Vb + SM_V;                // [8][16][36]

    const int tid  = threadIdx.x;
    const int lane = tid & 31;
    const int w    = tid >> 5;
    const int g    = lane >> 2;           // groupID 0..7
    const int c    = lane & 3;            // threadID_in_group 0..3
    const int head = blockIdx.x >> 3;
    const int rt   = blockIdx.x & 7;
    const int row0 = rt * BR;
    const int q0   = w * 16;              // warp's query-row block within CTA

    const float* Qh = Qg + ((size_t)head * Nq + row0) * D;
    const float* Kh = Kg + (size_t)head * Nq * D;
    const float* Vh = Vg + (size_t)head * Nq * D;

    // ---- stage Q (128x128), RNA-rounded to tf32 ----
    #pragma unroll
    for (int i = 0; i < 16; ++i) {
        int f  = tid + i * TPB;
        int r  = f >> 5, c4 = (f & 31) * 4;
        float4 v = *(const float4*)(Qh + r * D + c4);
        float* d = Qs + r * QS + c4;
        d[0] = to_tf32(v.x); d[1] = to_tf32(v.y);
        d[2] = to_tf32(v.z); d[3] = to_tf32(v.w);
    }
    // ---- stage K tile 0 (RNA-rounded) + V tile 0 (cp.async, truncation ok) ----
    #pragma unroll
    for (int i = 0; i < 4; ++i) {
        int f  = tid + i * TPB;
        int r  = f >> 5, c4 = (f & 31) * 4;
        float4 v = *(const float4*)(Kh + r * D + c4);
        float* d = Kb + r * KSs + c4;
        d[0] = to_tf32(v.x); d[1] = to_tf32(v.y);
        d[2] = to_tf32(v.z); d[3] = to_tf32(v.w);
        cp_async16(smem_u32(Vb + r * VS + c4), Vh + r * D + c4);
    }
    asm volatile("cp.async.commit_group;" ::: "memory");

    float o[16][4];
    #pragma unroll
    for (int j = 0; j < 16; ++j)
        #pragma unroll
        for (int i = 0; i < 4; ++i) o[j][i] = 0.f;
    float m0 = -9e15f, m1 = -9e15f, l0 = 0.f, l1 = 0.f;
    int buf = 0;

    float* Pw = Pa + w * 16 * PS;

    #pragma unroll 1
    for (int kt = 0; kt < NT; ++kt) {
        asm volatile("cp.async.wait_group 0;" ::: "memory");
        __syncthreads();

        const float* Kc = Kb + buf * BC * KSs;
        const float* Vc = Vb + buf * BC * VS;
        float*       Kn = Kb + (buf ^ 1) * BC * KSs;
        float*       Vn = Vb + (buf ^ 1) * BC * VS;

        // prefetch next K into registers, launch next V cp.async
        float4 kp[4];
        const bool more = (kt + 1 < NT);
        if (more) {
            const float* Kg2 = Kh + (size_t)(kt + 1) * BC * D;
            const float* Vg2 = Vh + (size_t)(kt + 1) * BC * D;
            #pragma unroll
            for (int i = 0; i < 4; ++i) {
                int f = tid + i * TPB;
                int r = f >> 5, c4 = (f & 31) * 4;
                kp[i] = *(const float4*)(Kg2 + r * D + c4);
                cp_async16(smem_u32(Vn + r * VS + c4), Vg2 + r * D + c4);
            }
            asm volatile("cp.async.commit_group;" ::: "memory");
        }

        // ---- S = Q K^T : warp tile 16x32, 4 n-tiles, 16 k-steps ----
        float s[4][4];
        #pragma unroll
        for (int j = 0; j < 4; ++j)
            #pragma unroll
            for (int i = 0; i < 4; ++i) s[j][i] = 0.f;

        const float* qa  = Qs + (q0 + g) * QS + c;
        const float* kb0 = Kc + g * KSs + c;
        #pragma unroll
        for (int ks = 0; ks < 16; ++ks) {
            uint32_t a0 = fu(qa[8 * ks]);
            uint32_t a1 = fu(qa[8 * QS + 8 * ks]);
            uint32_t a2 = fu(qa[8 * ks + 4]);
            uint32_t a3 = fu(qa[8 * QS + 8 * ks + 4]);
            #pragma unroll
            for (int j = 0; j < 4; ++j) {
                uint32_t b0 = fu(kb0[j * 8 * KSs + 8 * ks]);
                uint32_t b1 = fu(kb0[j * 8 * KSs + 8 * ks + 4]);
                mma_tf32(s[j][0], s[j][1], s[j][2], s[j][3], a0, a1, a2, a3, b0, b1);
            }
        }

        // ---- mask + scale (exact reference constants) ----
        const int qr = row0 + q0 + g;
        #pragma unroll
        for (int j = 0; j < 4; ++j) {
            int gc = kt * BC + 8 * j + 2 * c;
            int2 ma = *(const int2*)(adj + (size_t)qr * Nq + gc);
            int2 mb = *(const int2*)(adj + (size_t)(qr + 8) * Nq + gc);
            s[j][0] = (ma.x > 0) ? s[j][0] * 0.125f : -9e15f;
            s[j][1] = (ma.y > 0) ? s[j][1] * 0.125f : -9e15f;
            s[j][2] = (mb.x > 0) ? s[j][2] * 0.125f : -9e15f;
            s[j][3] = (mb.y > 0) ? s[j][3] * 0.125f : -9e15f;
        }

        // ---- online softmax: rows g (slots 0,1) and g+8 (slots 2,3); reduce over 4-lane group ----
        float tm0 = fmaxf(fmaxf(s[0][0], s[0][1]), fmaxf(s[1][0], s[1][1]));
        tm0 = fmaxf(tm0, fmaxf(fmaxf(s[2][0], s[2][1]), fmaxf(s[3][0], s[3][1])));
        float tm1 = fmaxf(fmaxf(s[0][2], s[0][3]), fmaxf(s[1][2], s[1][3]));
        tm1 = fmaxf(tm1, fmaxf(fmaxf(s[2][2], s[2][3]), fmaxf(s[3][2], s[3][3])));
        tm0 = fmaxf(tm0, __shfl_xor_sync(0xffffffffu, tm0, 1));
        tm0 = fmaxf(tm0, __shfl_xor_sync(0xffffffffu, tm0, 2));
        tm1 = fmaxf(tm1, __shfl_xor_sync(0xffffffffu, tm1, 1));
        tm1 = fmaxf(tm1, __shfl_xor_sync(0xffffffffu, tm1, 2));

        float mn0 = fmaxf(m0, tm0), mn1 = fmaxf(m1, tm1);
        float sc0 = exp_fast(m0 - mn0), sc1 = exp_fast(m1 - mn1);
        m0 = mn0; m1 = mn1;

        float p[4][4];
        float rs0 = 0.f, rs1 = 0.f;
        #pragma unroll
        for (int j = 0; j < 4; ++j) {
            p[j][0] = exp_fast(s[j][0] - mn0);
            p[j][1] = exp_fast(s[j][1] - mn0);
            p[j][2] = exp_fast(s[j][2] - mn1);
            p[j][3] = exp_fast(s[j][3] - mn1);
            rs0 += p[j][0] + p[j][1];
            rs1 += p[j][2] + p[j][3];
        }
        rs0 += __shfl_xor_sync(0xffffffffu, rs0, 1);
        rs0 += __shfl_xor_sync(0xffffffffu, rs0, 2);
        rs1 += __shfl_xor_sync(0xffffffffu, rs1, 1);
        rs1 += __shfl_xor_sync(0xffffffffu, rs1, 2);
        l0 = l0 * sc0 + rs0;
        l1 = l1 * sc1 + rs1;

        #pragma unroll
        for (int j2 = 0; j2 < 16; ++j2) {
            o[j2][0] *= sc0; o[j2][1] *= sc0;
            o[j2][2] *= sc1; o[j2][3] *= sc1;
        }

        // ---- P -> warp-private smem (A-fragment relayout), warp-local only ----
        #pragma unroll
        for (int j = 0; j < 4; ++j) {
            *(float2*)(Pw + g * PS + 8 * j + 2 * c)       = make_float2(p[j][0], p[j][1]);
            *(float2*)(Pw + (g + 8) * PS + 8 * j + 2 * c) = make_float2(p[j][2], p[j][3]);
        }
        __syncwarp();

        // ---- O += P @ V : 16 n-tiles over d=128, 4 k-steps ----
        const float* pa  = Pw + g * PS + c;
        const float* vb0 = Vc + c * VS + g;
        #pragma unroll
        for (int kk = 0; kk < 4; ++kk) {
            uint32_t a0 = fu(pa[8 * kk]);
            uint32_t a1 = fu(pa[8 * PS + 8 * kk]);
            uint32_t a2 = fu(pa[8 * kk + 4]);
            uint32_t a3 = fu(pa[8 * PS + 8 * kk + 4]);
            #pragma unroll
            for (int j2 = 0; j2 < 16; ++j2) {
                uint32_t b0 = fu(vb0[(8 * kk) * VS + 8 * j2]);
                uint32_t b1 = fu(vb0[(8 * kk + 4) * VS + 8 * j2]);
                mma_tf32(o[j2][0], o[j2][1], o[j2][2], o[j2][3], a0, a1, a2, a3, b0, b1);
            }
        }

        // ---- store prefetched K (RNA) into next buffer; safe: barrier at kt start ----
        if (more) {
            #pragma unroll
            for (int i = 0; i < 4; ++i) {
                int f = tid + i * TPB;
                int r = f >> 5, c4 = (f & 31) * 4;
                float* d = Kn + r * KSs + c4;
                d[0] = to_tf32(kp[i].x); d[1] = to_tf32(kp[i].y);
                d[2] = to_tf32(kp[i].z); d[3] = to_tf32(kp[i].w);
            }
        }
        buf ^= 1;
    }

    // ---- epilogue: normalize + store ----
    float inv0 = 1.0f / l0;
    float inv1 = 1.0f / l1;
    float* orow0 = Out + ((size_t)head * Nq + row0 + q0 + g) * D;
    float* orow1 = orow0 + 8 * D;
    #pragma unroll
    for (int j2 = 0; j2 < 16; ++j2) {
        *(float2*)(orow0 + 8 * j2 + 2 * c) = make_float2(o[j2][0] * inv0, o[j2][1] * inv0);
        *(float2*)(orow1 + 8 * j2 + 2 * c) = make_float2(o[j2][2] * inv1, o[j2][3] * inv1);
    }
}

extern "C" void kernel_launch(void* const* d_in, const int* in_sizes, int n_in,
                              void* d_out, int out_size)
{
    const float* Q   = (const float*)d_in[0];
    const float* K   = (const float*)d_in[1];
    const float* V   = (const float*)d_in[2];
    const int*   adj = (const int*)d_in[3];
    float*       out = (float*)d_out;

    cudaFuncSetAttribute(fa_tf32_kernel,
                         cudaFuncAttributeMaxDynamicSharedMemorySize, SMEM_BYTES);

    dim3 grid(64 * (Nq / BR));   // 64 heads * 8 row-tiles = 512 CTAs
    fa_tf32_kernel<<<grid, TPB, SMEM_BYTES>>>(Q, K, V, adj, out);
}